// round 3
// baseline (speedup 1.0000x reference)
#include <cuda_runtime.h>
#include <cstddef>

#define DIM 512
#define HID 2048
#define NBR 512
#define ND (NBR*DIM)
#define NSTEPS 8
#define SUBSTEPS 2

// ---------------- device scratch (static allocation, allowed) ----------------
__device__ float g_y[DIM];
__device__ float g_Dy[ND];
__device__ float g_a[HID];
__device__ float g_kdy[4*DIM];
__device__ float g_kDy[16*ND];      // [stage*4 + ksplit][ND]  (split-K partials)
__device__ float g_G[NBR*HID];

typedef unsigned long long u64;

// ---------------- packed f32x2 helpers (Blackwell FFMA2) ----------------
__device__ __forceinline__ u64 pack2(float lo, float hi) {
    u64 r; asm("mov.b64 %0, {%1, %2};" : "=l"(r) : "f"(lo), "f"(hi)); return r;
}
__device__ __forceinline__ u64 fma2(u64 a, u64 b, u64 c) {
    u64 d; asm("fma.rn.f32x2 %0, %1, %2, %3;" : "=l"(d) : "l"(a), "l"(b), "l"(c)); return d;
}
__device__ __forceinline__ float2 unpack2(u64 v) {
    float lo, hi; asm("mov.b64 {%0, %1}, %2;" : "=f"(lo), "=f"(hi) : "l"(v));
    return make_float2(lo, hi);
}

__device__ __forceinline__ float4 axpy4(float4 v, float c, float4 a, float4 b, float4 d, float4 e) {
    v.x += c*(a.x+b.x+d.x+e.x); v.y += c*(a.y+b.y+d.y+e.y);
    v.z += c*(a.z+b.z+d.z+e.z); v.w += c*(a.w+b.w+d.w+e.w);
    return v;
}

// ---------------- SGEMM 64x128 tile, 256 thr, 4x8 microtile on f32x2 ----------------
// C[M=512 x N] = A[512 x K] * B[K x N]  (all row-major), K covered per-z as k0..k0+512
// AXPY:  A_eff = A + c*(P0+P1+P2+P3)   (fused RK4 stage prep over split-K partials)
// EPI_G: out = s*u*(1 - a*u), s = 1-a^2, per-column a = avec[col]  (Jv + 0.5Hvv epilogue)
// A held transposed in smem; LDS.128 of 4 adjacent rows yields two f32x2 row-pairs
// directly (no pack movs on the A side).
template<bool AXPY, bool EPI_G>
__global__ void __launch_bounds__(256)
gemm64x128(const float* __restrict__ A, int lda,
           const float* __restrict__ P0, const float* __restrict__ P1,
           const float* __restrict__ P2, const float* __restrict__ P3,
           const float* __restrict__ ts, int interval, float cmul,
           const float* __restrict__ B, int ldb,
           const float* __restrict__ avec,
           float* __restrict__ Cbase, int ldc, int zstride)
{
    constexpr int KSUB = 512;
    __shared__ float As[2][16][64];    // transposed A tile (k-major)
    __shared__ float Bs[2][16][128];

    const int t  = threadIdx.x;
    const int rb = blockIdx.y * 64;
    const int cb = blockIdx.x * 128;
    const int z  = blockIdx.z;
    const int k0 = z * KSUB;
    float* __restrict__ C = Cbase + (size_t)z * zstride;

    float c = 0.f;
    if (AXPY) {
        float dt = (ts[interval+1] - ts[interval]) * (1.0f / SUBSTEPS);
        c = cmul * dt;
    }

    // A loader: thread t -> row (t&63), k-group ((t>>6)*4), 1 float4 per tile
    const int ar  = t & 63;
    const int akg = (t >> 6) * 4;
    const float* Arow = A + (size_t)(rb + ar) * lda + k0 + akg;
    const float *Q0 = nullptr, *Q1 = nullptr, *Q2 = nullptr, *Q3 = nullptr;
    if (AXPY) {
        size_t off = (size_t)(rb + ar) * lda + k0 + akg;  // partials share lda=512
        Q0 = P0 + off; Q1 = P1 + off; Q2 = P2 + off; Q3 = P3 + off;
    }
    // B loader: thread t -> rows (t>>5), (t>>5)+8; float4 col (t&31); coalesced
    const int brw = t >> 5;
    const int bc4 = t & 31;
    const float* Bp = B + (size_t)(k0 + brw) * ldb + cb + bc4 * 4;

    const int ty = t >> 4;   // 0..15 -> rows ty*4..ty*4+3
    const int tx = t & 15;   // 0..15 -> cols tx*4..+3 and 64+tx*4..+67

    u64 acc[2][8];           // [row-pair][col]; lanes = rows (2rp, 2rp+1) of ty*4+..
    #pragma unroll
    for (int rp = 0; rp < 2; rp++)
        #pragma unroll
        for (int j = 0; j < 8; j++) acc[rp][j] = 0ull;

    float4 sa, sp[4], sb[2];

    auto ldg_tile = [&](int kc) {
        sa = *(const float4*)(Arow + kc);
        if (AXPY) {
            sp[0] = *(const float4*)(Q0 + kc);
            sp[1] = *(const float4*)(Q1 + kc);
            sp[2] = *(const float4*)(Q2 + kc);
            sp[3] = *(const float4*)(Q3 + kc);
        }
        sb[0] = *(const float4*)(Bp + (size_t)kc * ldb);
        sb[1] = *(const float4*)(Bp + (size_t)(kc + 8) * ldb);
    };
    auto sts_tile = [&](int buf) {
        float4 v = sa;
        if (AXPY) v = axpy4(v, c, sp[0], sp[1], sp[2], sp[3]);
        As[buf][akg+0][ar] = v.x; As[buf][akg+1][ar] = v.y;
        As[buf][akg+2][ar] = v.z; As[buf][akg+3][ar] = v.w;
        *(float4*)&Bs[buf][brw][bc4*4]     = sb[0];
        *(float4*)&Bs[buf][brw + 8][bc4*4] = sb[1];
    };
    auto compute = [&](int buf) {
        #pragma unroll
        for (int k = 0; k < 16; k++) {
            // A: one LDS.128 = rows ty*4..+3 = two packed f32x2 row-pairs
            ulonglong2 ap = *(const ulonglong2*)&As[buf][k][ty*4];
            float4 b0 = *(const float4*)&Bs[buf][k][tx*4];
            float4 b1 = *(const float4*)&Bs[buf][k][64 + tx*4];
            u64 bd[8] = { pack2(b0.x,b0.x), pack2(b0.y,b0.y),
                          pack2(b0.z,b0.z), pack2(b0.w,b0.w),
                          pack2(b1.x,b1.x), pack2(b1.y,b1.y),
                          pack2(b1.z,b1.z), pack2(b1.w,b1.w) };
            #pragma unroll
            for (int j = 0; j < 8; j++) {
                acc[0][j] = fma2(ap.x, bd[j], acc[0][j]);
                acc[1][j] = fma2(ap.y, bd[j], acc[1][j]);
            }
        }
    };

    ldg_tile(0);
    sts_tile(0);
    __syncthreads();
    const int KIT = KSUB / 16;
    for (int it = 0; it < KIT; it++) {
        int buf = it & 1;
        bool more = (it + 1 < KIT);
        if (more) ldg_tile((it + 1) * 16);   // LDG in flight over compute
        compute(buf);
        if (more) sts_tile(buf ^ 1);
        __syncthreads();
    }

    // epilogue
    float aa[8] = {0,0,0,0,0,0,0,0};
    if (EPI_G) {
        float4 av0 = *(const float4*)(avec + cb + tx*4);
        float4 av1 = *(const float4*)(avec + cb + 64 + tx*4);
        aa[0]=av0.x; aa[1]=av0.y; aa[2]=av0.z; aa[3]=av0.w;
        aa[4]=av1.x; aa[5]=av1.y; aa[6]=av1.z; aa[7]=av1.w;
    }
    #pragma unroll
    for (int rp = 0; rp < 2; rp++) {
        float lo[8], hi[8];
        #pragma unroll
        for (int j = 0; j < 8; j++) {
            float2 u = unpack2(acc[rp][j]);
            lo[j] = u.x; hi[j] = u.y;
        }
        if (EPI_G) {
            #pragma unroll
            for (int j = 0; j < 8; j++) {
                float aH = aa[j];
                float s = 1.f - aH * aH;
                lo[j] = s * lo[j] * (1.f - aH * lo[j]);   // s*u + 0.5*(-2a*s)*u^2
                hi[j] = s * hi[j] * (1.f - aH * hi[j]);
            }
        }
        int m0 = rb + ty*4 + 2*rp;
        float* Crow0 = C + (size_t)m0 * ldc + cb;
        float* Crow1 = Crow0 + ldc;
        *(float4*)(Crow0 + tx*4)      = make_float4(lo[0],lo[1],lo[2],lo[3]);
        *(float4*)(Crow0 + 64 + tx*4) = make_float4(lo[4],lo[5],lo[6],lo[7]);
        *(float4*)(Crow1 + tx*4)      = make_float4(hi[0],hi[1],hi[2],hi[3]);
        *(float4*)(Crow1 + 64 + tx*4) = make_float4(hi[4],hi[5],hi[6],hi[7]);
    }
}

// ---------------- a = tanh((y + c*kprev) @ W1 + b1) ----------------
// 32 blocks x 256 thr; 4-way d-split + smem reduce; coalesced W1 rows.
__global__ void __launch_bounds__(256) hcalc_kernel(
    const float* __restrict__ y, const float* __restrict__ kprev,
    const float* __restrict__ ts, int interval, float cmul,
    const float* __restrict__ W1, const float* __restrict__ b1,
    float* __restrict__ aout)
{
    __shared__ float ysh[DIM];
    __shared__ float red[256];
    int t = threadIdx.x;
    float dt = (ts[interval+1] - ts[interval]) * (1.0f / SUBSTEPS);
    float c = cmul * dt;
    ysh[t]       = y[t]       + c * kprev[t];
    ysh[t + 256] = y[t + 256] + c * kprev[t + 256];
    __syncthreads();
    int ds = t >> 6;           // 0..3
    int jj = t & 63;
    int j = blockIdx.x * 64 + jj;
    const float* w = W1 + (size_t)(ds * 128) * HID + j;
    float h = 0.f;
    #pragma unroll 8
    for (int d = 0; d < 128; d++) h += ysh[ds*128 + d] * w[(size_t)d * HID];
    red[t] = h;
    __syncthreads();
    if (t < 64) {
        float hh = red[t] + red[t+64] + red[t+128] + red[t+192] + b1[j];
        aout[j] = tanhf(hh);
    }
}

// ---------------- dy = a @ W2 + b2 ----------------
// 16 blocks x 256 thr; 8-way h-split + smem reduce.
__global__ void __launch_bounds__(256) dycalc_kernel(
    const float* __restrict__ avec, const float* __restrict__ W2,
    const float* __restrict__ b2, float* __restrict__ dyout)
{
    __shared__ float red[256];
    int t = threadIdx.x;
    int hs = t >> 5;           // 0..7
    int dd = t & 31;
    int d = blockIdx.x * 32 + dd;
    const float* w  = W2 + (size_t)(hs * 256) * DIM + d;
    const float* av = avec + hs * 256;
    float acc = 0.f;
    #pragma unroll 8
    for (int h = 0; h < 256; h++) acc += av[h] * w[(size_t)h * DIM];
    red[t] = acc;
    __syncthreads();
    if (t < 32) {
        float s = 0.f;
        #pragma unroll
        for (int i = 0; i < 8; i++) s += red[dd + i*32];
        dyout[d] = s + b2[d];
    }
}

// ---------------- RK4 combine: u += dt/6 (k1 + 2k2 + 2k3 + k4) ----------------
// Sums the 4 split-K partials of each kDy inline (deterministic, no atomics).
__global__ void __launch_bounds__(256) combine_kernel(const float* __restrict__ ts, int interval)
{
    int i = blockIdx.x * 256 + threadIdx.x;
    float dt = (ts[interval+1] - ts[interval]) * (1.0f / SUBSTEPS);
    float w = dt * (1.0f / 6.0f);
    if (i < ND) {
        float s = 0.f;
        #pragma unroll
        for (int j = 0; j < 4; j++)
            s += (g_kDy[(size_t)(0*4+j)*ND + i] + g_kDy[(size_t)(3*4+j)*ND + i])
               + 2.f * (g_kDy[(size_t)(1*4+j)*ND + i] + g_kDy[(size_t)(2*4+j)*ND + i]);
        g_Dy[i] += w * s;
    } else if (i < ND + DIM) {
        int d = i - ND;
        g_y[d] += w * (g_kdy[d] + 2.f*g_kdy[DIM + d] + 2.f*g_kdy[2*DIM + d] + g_kdy[3*DIM + d]);
    }
}

// ---------------- driver ----------------
extern "C" void kernel_launch(void* const* d_in, const int* in_sizes, int n_in,
                              void* d_out, int out_size)
{
    (void)in_sizes; (void)n_in; (void)out_size;
    const float* ts  = (const float*)d_in[0];
    const float* y0  = (const float*)d_in[1];
    const float* Dy0 = (const float*)d_in[2];
    const float* W1  = (const float*)d_in[3];
    const float* b1  = (const float*)d_in[4];
    const float* W2  = (const float*)d_in[5];
    const float* b2  = (const float*)d_in[6];
    float* out = (float*)d_out;

    float *y, *Dy, *a, *kdy, *kDy, *G;
    cudaGetSymbolAddress((void**)&y,   g_y);
    cudaGetSymbolAddress((void**)&Dy,  g_Dy);
    cudaGetSymbolAddress((void**)&a,   g_a);
    cudaGetSymbolAddress((void**)&kdy, g_kdy);
    cudaGetSymbolAddress((void**)&kDy, g_kDy);
    cudaGetSymbolAddress((void**)&G,   g_G);

    // init state + t=0 output slice
    cudaMemcpyAsync(y,  y0,  DIM*sizeof(float), cudaMemcpyDeviceToDevice, 0);
    cudaMemcpyAsync(Dy, Dy0, (size_t)ND*sizeof(float), cudaMemcpyDeviceToDevice, 0);
    cudaMemcpyAsync(out, y0, DIM*sizeof(float), cudaMemcpyDeviceToDevice, 0);
    cudaMemcpyAsync(out + DIM, Dy0, (size_t)ND*sizeof(float), cudaMemcpyDeviceToDevice, 0);

    const float CM[4] = {0.f, 0.5f, 0.5f, 1.f};
    for (int interval = 0; interval < NSTEPS; interval++) {
        for (int sub = 0; sub < SUBSTEPS; sub++) {
            for (int s = 0; s < 4; s++) {
                const float* kprev = s ? (kdy + (size_t)(s-1)*DIM) : y;
                hcalc_kernel<<<32, 256>>>(y, kprev, ts, interval, CM[s], W1, b1, a);
                dycalc_kernel<<<16, 256>>>(a, W2, b2, kdy + (size_t)s*DIM);
                if (s == 0) {
                    gemm64x128<false, true><<<dim3(16,8,1), 256>>>(
                        Dy, DIM, nullptr, nullptr, nullptr, nullptr,
                        ts, interval, 0.f, W1, HID, a, G, HID, 0);
                } else {
                    const float* pb = kDy + (size_t)(s-1)*4*ND;
                    gemm64x128<true, true><<<dim3(16,8,1), 256>>>(
                        Dy, DIM, pb, pb + (size_t)ND, pb + 2*(size_t)ND, pb + 3*(size_t)ND,
                        ts, interval, CM[s], W1, HID, a, G, HID, 0);
                }
                gemm64x128<false, false><<<dim3(4,8,4), 256>>>(
                    G, HID, nullptr, nullptr, nullptr, nullptr,
                    ts, interval, 0.f, W2, DIM, nullptr,
                    kDy + (size_t)s*4*ND, DIM, ND);
            }
            combine_kernel<<<(ND + DIM + 255)/256, 256>>>(ts, interval);
        }
        float* dst = out + (size_t)(interval+1) * (1 + NBR) * DIM;
        cudaMemcpyAsync(dst, y, DIM*sizeof(float), cudaMemcpyDeviceToDevice, 0);
        cudaMemcpyAsync(dst + DIM, Dy, (size_t)ND*sizeof(float), cudaMemcpyDeviceToDevice, 0);
    }
}

// round 4
// speedup vs baseline: 1.9502x; 1.9502x over previous
#include <cuda_runtime.h>
#include <cstddef>

#define DIM 512
#define HID 2048
#define NBR 512
#define ND (NBR*DIM)
#define NSTEPS 8
#define SUBSTEPS 2

// ---------------- device scratch (static allocation, allowed) ----------------
__device__ float g_y[DIM];
__device__ float g_Dy[ND];
__device__ float g_a[HID];
__device__ float g_kdy[4*DIM];
__device__ float g_kDy[4*ND];       // reduced kDy per stage
__device__ float g_kDyP[8*ND];      // GEMM-C split-K partials (z=8)
__device__ float g_G[2*(size_t)NBR*HID];  // GEMM-G split-K partials (z=2), raw (pre-epilogue)

typedef unsigned long long u64;

// ---------------- packed f32x2 helpers (Blackwell FFMA2) ----------------
__device__ __forceinline__ u64 pack2(float lo, float hi) {
    u64 r; asm("mov.b64 %0, {%1, %2};" : "=l"(r) : "f"(lo), "f"(hi)); return r;
}
__device__ __forceinline__ u64 fma2(u64 a, u64 b, u64 c) {
    u64 d; asm("fma.rn.f32x2 %0, %1, %2, %3;" : "=l"(d) : "l"(a), "l"(b), "l"(c)); return d;
}
__device__ __forceinline__ float2 unpack2(u64 v) {
    float lo, hi; asm("mov.b64 {%0, %1}, %2;" : "=f"(lo), "=f"(hi) : "l"(v));
    return make_float2(lo, hi);
}

// epilogue of the Jv+0.5Hvv map, applied elementwise: v = s*u*(1-a*u), s=1-a^2
__device__ __forceinline__ float4 epi4(float4 u, float4 a) {
    float4 v;
    v.x = (1.f - a.x*a.x) * u.x * (1.f - a.x*u.x);
    v.y = (1.f - a.y*a.y) * u.y * (1.f - a.y*u.y);
    v.z = (1.f - a.z*a.z) * u.z * (1.f - a.z*u.z);
    v.w = (1.f - a.w*a.w) * u.w * (1.f - a.w*u.w);
    return v;
}
__device__ __forceinline__ float4 add4(float4 a, float4 b) {
    return make_float4(a.x+b.x, a.y+b.y, a.z+b.z, a.w+b.w);
}
__device__ __forceinline__ float4 axpy1_4(float4 v, float c, float4 p) {
    return make_float4(v.x+c*p.x, v.y+c*p.y, v.z+c*p.z, v.w+c*p.w);
}

// ---------------- SGEMM 64x128 tile, 128 thr, 8x8 microtile on f32x2 ----------------
// C[64r x 128c] += A[64 x KSUB] * B[KSUB x 128], KSUB=256 per blockIdx.z; partials out.
// AMODE 0: A plain
// AMODE 1: A_eff = A + c*P0        (RK4 stage prep, single reduced partial)
// AMODE 2: A_eff = epi(A + A2, avec[k])  (sum GEMM-G split-K partials + nonlinear epilogue)
// A kept transposed in smem; LDS.128 yields 2 packed f32x2 row-pairs directly.
// Ratio per thread per k: 4 LDS.128 : 32 FFMA2 = 1:8 (fma/smem balanced at 2 warps/SMSP).
template<int AMODE>
__global__ void __launch_bounds__(128, 2)
gemm64x128(const float* __restrict__ A, const float* __restrict__ A2, int lda,
           const float* __restrict__ ts, int interval, float cmul,
           const float* __restrict__ avec,
           const float* __restrict__ B, int ldb,
           float* __restrict__ Cbase, int ldc, size_t zstride)
{
    constexpr int KSUB = 256;
    __shared__ float As[2][16][64];    // transposed A tile (k-major)
    __shared__ float Bs[2][16][128];

    const int t  = threadIdx.x;
    const int rb = blockIdx.y * 64;
    const int cb = blockIdx.x * 128;
    const int z  = blockIdx.z;
    const int k0 = z * KSUB;
    float* __restrict__ C = Cbase + (size_t)z * zstride;

    float c = 0.f;
    if (AMODE == 1) {
        float dt = (ts[interval+1] - ts[interval]) * (1.0f / SUBSTEPS);
        c = cmul * dt;
    }

    // A loader: thread t -> row (t&63), k-group ((t>>6)*8), 2 float4 per tile
    const int ar  = t & 63;
    const int akg = (t >> 6) * 8;
    const float* Arow = A + (size_t)(rb + ar) * lda + k0 + akg;
    const float* A2row = (AMODE >= 1) ? (A2 + (size_t)(rb + ar) * lda + k0 + akg) : nullptr;
    // B loader: thread t -> rows (t>>5)+4i, float4 col (t&31); coalesced 512B/warp
    const int brw = t >> 5;
    const int bc4 = t & 31;
    const float* Bp = B + (size_t)(k0 + brw) * ldb + cb + bc4 * 4;

    const int ty = t >> 4;   // 0..7  -> rows ty*8..ty*8+7
    const int tx = t & 15;   // 0..15 -> cols tx*4..+3 and 64+tx*4..+67

    u64 acc[4][8];           // [row-pair][col]; lanes = rows (ty*8+2rp, +2rp+1)
    #pragma unroll
    for (int rp = 0; rp < 4; rp++)
        #pragma unroll
        for (int j = 0; j < 8; j++) acc[rp][j] = 0ull;

    float4 sa0, sa1, sq0, sq1, sv0, sv1, sb[4];

    auto ldg_tile = [&](int kc) {
        sa0 = *(const float4*)(Arow + kc);
        sa1 = *(const float4*)(Arow + kc + 4);
        if (AMODE >= 1) {
            sq0 = *(const float4*)(A2row + kc);
            sq1 = *(const float4*)(A2row + kc + 4);
        }
        if (AMODE == 2) {
            sv0 = *(const float4*)(avec + k0 + kc + akg);
            sv1 = *(const float4*)(avec + k0 + kc + akg + 4);
        }
        #pragma unroll
        for (int i = 0; i < 4; i++)
            sb[i] = *(const float4*)(Bp + (size_t)(kc + 4*i) * ldb);
    };
    auto sts_tile = [&](int buf) {
        float4 v0 = sa0, v1 = sa1;
        if (AMODE == 1) {
            v0 = axpy1_4(v0, c, sq0);
            v1 = axpy1_4(v1, c, sq1);
        }
        if (AMODE == 2) {
            v0 = epi4(add4(v0, sq0), sv0);
            v1 = epi4(add4(v1, sq1), sv1);
        }
        As[buf][akg+0][ar] = v0.x; As[buf][akg+1][ar] = v0.y;
        As[buf][akg+2][ar] = v0.z; As[buf][akg+3][ar] = v0.w;
        As[buf][akg+4][ar] = v1.x; As[buf][akg+5][ar] = v1.y;
        As[buf][akg+6][ar] = v1.z; As[buf][akg+7][ar] = v1.w;
        #pragma unroll
        for (int i = 0; i < 4; i++)
            *(float4*)&Bs[buf][brw + 4*i][bc4*4] = sb[i];
    };
    auto compute = [&](int buf) {
        #pragma unroll
        for (int k = 0; k < 16; k++) {
            // A: two LDS.128 = rows ty*8..+7 = four packed f32x2 row-pairs
            ulonglong2 a01 = *(const ulonglong2*)&As[buf][k][ty*8];
            ulonglong2 a23 = *(const ulonglong2*)&As[buf][k][ty*8 + 4];
            float4 b0 = *(const float4*)&Bs[buf][k][tx*4];
            float4 b1 = *(const float4*)&Bs[buf][k][64 + tx*4];
            u64 bd[8] = { pack2(b0.x,b0.x), pack2(b0.y,b0.y),
                          pack2(b0.z,b0.z), pack2(b0.w,b0.w),
                          pack2(b1.x,b1.x), pack2(b1.y,b1.y),
                          pack2(b1.z,b1.z), pack2(b1.w,b1.w) };
            u64 ap[4] = { a01.x, a01.y, a23.x, a23.y };
            #pragma unroll
            for (int rp = 0; rp < 4; rp++)
                #pragma unroll
                for (int j = 0; j < 8; j++)
                    acc[rp][j] = fma2(ap[rp], bd[j], acc[rp][j]);
        }
    };

    ldg_tile(0);
    sts_tile(0);
    __syncthreads();
    const int KIT = KSUB / 16;
    for (int it = 0; it < KIT; it++) {
        int buf = it & 1;
        bool more = (it + 1 < KIT);
        if (more) ldg_tile((it + 1) * 16);   // LDG in flight over compute
        compute(buf);
        if (more) sts_tile(buf ^ 1);
        __syncthreads();
    }

    // epilogue: raw partial store (no nonlinearity here; it lives in the consumer's loader)
    #pragma unroll
    for (int rp = 0; rp < 4; rp++) {
        float lo[8], hi[8];
        #pragma unroll
        for (int j = 0; j < 8; j++) {
            float2 u = unpack2(acc[rp][j]);
            lo[j] = u.x; hi[j] = u.y;
        }
        int m0 = rb + ty*8 + 2*rp;
        float* Crow0 = C + (size_t)m0 * ldc + cb;
        float* Crow1 = Crow0 + ldc;
        *(float4*)(Crow0 + tx*4)      = make_float4(lo[0],lo[1],lo[2],lo[3]);
        *(float4*)(Crow0 + 64 + tx*4) = make_float4(lo[4],lo[5],lo[6],lo[7]);
        *(float4*)(Crow1 + tx*4)      = make_float4(hi[0],hi[1],hi[2],hi[3]);
        *(float4*)(Crow1 + 64 + tx*4) = make_float4(hi[4],hi[5],hi[6],hi[7]);
    }
}

// ---------------- a = tanh((y + c*kprev) @ W1 + b1) ----------------
__global__ void __launch_bounds__(256) hcalc_kernel(
    const float* __restrict__ y, const float* __restrict__ kprev,
    const float* __restrict__ ts, int interval, float cmul,
    const float* __restrict__ W1, const float* __restrict__ b1,
    float* __restrict__ aout)
{
    __shared__ float ysh[DIM];
    __shared__ float red[256];
    int t = threadIdx.x;
    float dt = (ts[interval+1] - ts[interval]) * (1.0f / SUBSTEPS);
    float c = cmul * dt;
    ysh[t]       = y[t]       + c * kprev[t];
    ysh[t + 256] = y[t + 256] + c * kprev[t + 256];
    __syncthreads();
    int ds = t >> 6;           // 0..3
    int jj = t & 63;
    int j = blockIdx.x * 64 + jj;
    const float* w = W1 + (size_t)(ds * 128) * HID + j;
    float h = 0.f;
    #pragma unroll 8
    for (int d = 0; d < 128; d++) h += ysh[ds*128 + d] * w[(size_t)d * HID];
    red[t] = h;
    __syncthreads();
    if (t < 64) {
        float hh = red[t] + red[t+64] + red[t+128] + red[t+192] + b1[j];
        aout[j] = tanhf(hh);
    }
}

// ---------------- dy = a @ W2 + b2 ----------------
__global__ void __launch_bounds__(256) dycalc_kernel(
    const float* __restrict__ avec, const float* __restrict__ W2,
    const float* __restrict__ b2, float* __restrict__ dyout)
{
    __shared__ float red[256];
    int t = threadIdx.x;
    int hs = t >> 5;           // 0..7
    int dd = t & 31;
    int d = blockIdx.x * 32 + dd;
    const float* w  = W2 + (size_t)(hs * 256) * DIM + d;
    const float* av = avec + hs * 256;
    float acc = 0.f;
    #pragma unroll 8
    for (int h = 0; h < 256; h++) acc += av[h] * w[(size_t)h * DIM];
    red[t] = acc;
    __syncthreads();
    if (t < 32) {
        float s = 0.f;
        #pragma unroll
        for (int i = 0; i < 8; i++) s += red[dd + i*32];
        dyout[d] = s + b2[d];
    }
}

// ---------------- reduce the 8 GEMM-C split-K partials -> kDy[stage] ----------------
__global__ void __launch_bounds__(256) reduce_kernel(float* __restrict__ dst)
{
    int i = blockIdx.x * 256 + threadIdx.x;
    float s = 0.f;
    #pragma unroll
    for (int zz = 0; zz < 8; zz++) s += g_kDyP[(size_t)zz*ND + i];
    dst[i] = s;
}

// ---------------- RK4 combine: u += dt/6 (k1 + 2k2 + 2k3 + k4) ----------------
__global__ void __launch_bounds__(256) combine_kernel(const float* __restrict__ ts, int interval)
{
    int i = blockIdx.x * 256 + threadIdx.x;
    float dt = (ts[interval+1] - ts[interval]) * (1.0f / SUBSTEPS);
    float w = dt * (1.0f / 6.0f);
    if (i < ND) {
        float s = (g_kDy[i] + g_kDy[3*(size_t)ND + i])
                + 2.f * (g_kDy[(size_t)ND + i] + g_kDy[2*(size_t)ND + i]);
        g_Dy[i] += w * s;
    } else if (i < ND + DIM) {
        int d = i - ND;
        g_y[d] += w * (g_kdy[d] + 2.f*g_kdy[DIM + d] + 2.f*g_kdy[2*DIM + d] + g_kdy[3*DIM + d]);
    }
}

// ---------------- driver ----------------
extern "C" void kernel_launch(void* const* d_in, const int* in_sizes, int n_in,
                              void* d_out, int out_size)
{
    (void)in_sizes; (void)n_in; (void)out_size;
    const float* ts  = (const float*)d_in[0];
    const float* y0  = (const float*)d_in[1];
    const float* Dy0 = (const float*)d_in[2];
    const float* W1  = (const float*)d_in[3];
    const float* b1  = (const float*)d_in[4];
    const float* W2  = (const float*)d_in[5];
    const float* b2  = (const float*)d_in[6];
    float* out = (float*)d_out;

    float *y, *Dy, *a, *kdy, *kDy, *kDyP, *G;
    cudaGetSymbolAddress((void**)&y,    g_y);
    cudaGetSymbolAddress((void**)&Dy,   g_Dy);
    cudaGetSymbolAddress((void**)&a,    g_a);
    cudaGetSymbolAddress((void**)&kdy,  g_kdy);
    cudaGetSymbolAddress((void**)&kDy,  g_kDy);
    cudaGetSymbolAddress((void**)&kDyP, g_kDyP);
    cudaGetSymbolAddress((void**)&G,    g_G);

    // init state + t=0 output slice
    cudaMemcpyAsync(y,  y0,  DIM*sizeof(float), cudaMemcpyDeviceToDevice, 0);
    cudaMemcpyAsync(Dy, Dy0, (size_t)ND*sizeof(float), cudaMemcpyDeviceToDevice, 0);
    cudaMemcpyAsync(out, y0, DIM*sizeof(float), cudaMemcpyDeviceToDevice, 0);
    cudaMemcpyAsync(out + DIM, Dy0, (size_t)ND*sizeof(float), cudaMemcpyDeviceToDevice, 0);

    const float CM[4] = {0.f, 0.5f, 0.5f, 1.f};
    const size_t GSTR = (size_t)NBR * HID;
    for (int interval = 0; interval < NSTEPS; interval++) {
        for (int sub = 0; sub < SUBSTEPS; sub++) {
            for (int s = 0; s < 4; s++) {
                const float* kprev = s ? (kdy + (size_t)(s-1)*DIM) : y;
                hcalc_kernel<<<32, 256>>>(y, kprev, ts, interval, CM[s], W1, b1, a);
                dycalc_kernel<<<16, 256>>>(a, W2, b2, kdy + (size_t)s*DIM);
                // GEMM-G: [512 x 2048] = A_eff[512x512] @ W1, split-K z=2, raw partials
                if (s == 0) {
                    gemm64x128<0><<<dim3(16,8,2), 128>>>(
                        Dy, nullptr, DIM, ts, interval, 0.f, nullptr,
                        W1, HID, G, HID, GSTR);
                } else {
                    gemm64x128<1><<<dim3(16,8,2), 128>>>(
                        Dy, kDy + (size_t)(s-1)*ND, DIM, ts, interval, CM[s], nullptr,
                        W1, HID, G, HID, GSTR);
                }
                // GEMM-C: [512 x 512] = epi(G0+G1, a) @ W2, split-K z=8, raw partials
                gemm64x128<2><<<dim3(4,8,8), 128>>>(
                    G, G + GSTR, HID, ts, interval, 0.f, a,
                    W2, DIM, kDyP, DIM, (size_t)ND);
                // collapse 8 partials -> kDy[s]
                reduce_kernel<<<ND/256, 256>>>(kDy + (size_t)s*ND);
            }
            combine_kernel<<<(ND + DIM + 255)/256, 256>>>(ts, interval);
        }
        float* dst = out + (size_t)(interval+1) * (1 + NBR) * DIM;
        cudaMemcpyAsync(dst, y, DIM*sizeof(float), cudaMemcpyDeviceToDevice, 0);
        cudaMemcpyAsync(dst + DIM, Dy, (size_t)ND*sizeof(float), cudaMemcpyDeviceToDevice, 0);
    }
}

// round 6
// speedup vs baseline: 2.5939x; 1.3301x over previous
#include <cuda_runtime.h>
#include <cstddef>
#include <cstdint>

#define DIM 512
#define HID 2048
#define NBR 512
#define ND (NBR*DIM)
#define NSTEPS 8
#define SUBSTEPS 2

// ---------------- device scratch (static allocation, allowed) ----------------
__device__ float g_y[DIM];
__device__ float g_Dy[ND];
__device__ float g_a[HID];
__device__ float g_kdy[4*DIM];
__device__ float g_kDy[4*ND];                 // reduced kDy per stage
__device__ float g_kDyP[8*ND];                // GEMM-C split-K partials (z=8)
__device__ float g_G[2*(size_t)NBR*HID];      // GEMM-G split-K partials (z=2), raw
__device__ float g_AhG[ND],       g_AlG[ND];        // tf32-split A for GEMM-G
__device__ float g_AhC[NBR*HID],  g_AlC[NBR*HID];   // tf32-split A for GEMM-C
__device__ float g_W1Th[(size_t)HID*DIM], g_W1Tl[(size_t)HID*DIM];  // W1^T split [2048x512]
__device__ float g_W2Th[(size_t)DIM*HID], g_W2Tl[(size_t)DIM*HID];  // W2^T split [512x2048]

// ---------------- PTX helpers (all sm_80 family-common; NO tcgen05) ----------------
static __device__ __forceinline__ uint32_t s2u(const void* p) {
    uint32_t a;
    asm("{ .reg .u64 t; cvta.to.shared.u64 t, %1; cvt.u32.u64 %0, t; }" : "=r"(a) : "l"(p));
    return a;
}
static __device__ __forceinline__ void cp16(uint32_t s, const void* g) {
    asm volatile("cp.async.cg.shared.global [%0], [%1], 16;" :: "r"(s), "l"(g));
}
static __device__ __forceinline__ uint32_t swz(uint32_t o) { return o ^ ((o >> 3) & 0x70); }

static __device__ __forceinline__ void ldsm4(uint32_t* r, uint32_t addr) {
    asm volatile("ldmatrix.sync.aligned.m8n8.x4.shared.b16 {%0,%1,%2,%3}, [%4];"
                 : "=r"(r[0]), "=r"(r[1]), "=r"(r[2]), "=r"(r[3]) : "r"(addr));
}
static __device__ __forceinline__ void mma8(float* c, const uint32_t* a, const uint32_t* b) {
    asm volatile("mma.sync.aligned.m16n8k8.row.col.f32.tf32.tf32.f32 "
                 "{%0,%1,%2,%3}, {%4,%5,%6,%7}, {%8,%9}, {%0,%1,%2,%3};"
                 : "+f"(c[0]), "+f"(c[1]), "+f"(c[2]), "+f"(c[3])
                 : "r"(a[0]), "r"(a[1]), "r"(a[2]), "r"(a[3]), "r"(b[0]), "r"(b[1]));
}

// tf32 hi/lo split: x ≈ h + l, both tf32-representable; product error ~2^-21
static __device__ __forceinline__ void tf32split(float x, float& h, float& l) {
    uint32_t hb; asm("cvt.rna.tf32.f32 %0, %1;" : "=r"(hb) : "f"(x));
    float hf = __uint_as_float(hb);
    float r = x - hf;
    uint32_t lb; asm("cvt.rna.tf32.f32 %0, %1;" : "=r"(lb) : "f"(r));
    h = hf; l = __uint_as_float(lb);
}

// ---------------- mma.sync tf32 GEMM, 3-pass split: AhBh + AlBh + AhBl ----------------
// C[z](128m x 128n) partial over KSUB=256. A:[M x Ktot] k-major h/l. B:[N x Ktot] k-major h/l.
// 256 thr = 8 warps (2m x 4n), warp tile 64x32 = 4x4 m16n8 mma tiles, fp32 reg accum.
// ldmatrix.x4.b16 on f32 data: the b16 8x8 fragment (lane l -> row l>>2, 4B chunk l&3)
// viewed as f32 gives exactly the tf32 m16n8k8 A (row) and B (col) fragments.
#define KCH 32
#define NCH 8                      // KSUB/KCH
#define KSUB 256
#define TILE_B (128*KCH*4)         // 16 KB
#define BUF_B (4*TILE_B)           // Ah,Al,Bh,Bl
#define GEMM_SMEM (2*BUF_B)        // 128 KB double-buffered

__global__ void __launch_bounds__(256, 1)
gemm_mma(const float* __restrict__ Ah, const float* __restrict__ Al, int lda,
         const float* __restrict__ Bh, const float* __restrict__ Bl, int ldb,
         float* __restrict__ Cbase, int ldc, size_t zstride)
{
    extern __shared__ __align__(1024) char smem[];
    const uint32_t sb = s2u(smem);
    const int t = threadIdx.x, lane = t & 31, wid = t >> 5;
    const int nb = blockIdx.x, mb = blockIdx.y, z = blockIdx.z;
    const int kbase = z * KSUB;
    const int m0w = (wid & 1) * 64, n0w = (wid >> 1) * 32;

    // ldmatrix lane geometry (precompute swizzle rotation per tile-row)
    // A x4 covering one 16x8 tile: lanes 0-7 rows m..m+7 half0; 8-15 rows m+8.. half0?
    //   order: m0 rows0-7 k0-3 | rows8-15 k0-3 | rows0-7 k4-7 | rows8-15 k4-7
    const int rAl = (lane & 7) + ((lane >> 3) & 1) * 8;   // + m0w + i*16
    const int hA  = (lane >> 4) * 16;                     // k-half byte offset
    // B x4 covering two 8-wide n-tiles: rows n..n+7 h0 | h1 | rows n+8..n+15 h0 | h1
    const int rBl = (lane & 7) + ((lane >> 4) & 1) * 8;   // + n0w + jp*16
    const int hB  = ((lane >> 3) & 1) * 16;
    uint32_t rowA[4], crA[4], rowB[2], crB[2];
    #pragma unroll
    for (int i = 0; i < 4; i++) {
        int row = m0w + i * 16 + rAl;
        rowA[i] = (uint32_t)row * 128u; crA[i] = (uint32_t)(row & 7) * 16u;
    }
    #pragma unroll
    for (int jp = 0; jp < 2; jp++) {
        int row = n0w + jp * 16 + rBl;
        rowB[jp] = (uint32_t)row * 128u; crB[jp] = (uint32_t)(row & 7) * 16u;
    }

    float acc[4][4][4];
    #pragma unroll
    for (int i = 0; i < 4; i++)
        #pragma unroll
        for (int j = 0; j < 4; j++)
            #pragma unroll
            for (int q = 0; q < 4; q++) acc[i][j][q] = 0.f;

    // one tile = 128 rows x 32 floats; 256 thr x 4 x 16B, coalesced 128B runs in gmem
    auto load_tile = [&](const float* src, int rowbase, int ld, int k0, uint32_t sdst) {
        #pragma unroll
        for (int i = 0; i < 4; i++) {
            int id = i * 256 + t;
            int r = id >> 3, c = id & 7;
            cp16(sdst + swz((uint32_t)(r * 128 + c * 16)),
                 src + (size_t)(rowbase + r) * ld + k0 + c * 4);
        }
    };
    auto load_chunk = [&](int ch, int buf) {
        int k0 = kbase + ch * KCH;
        uint32_t b = sb + buf * BUF_B;
        load_tile(Ah, mb * 128, lda, k0, b);
        load_tile(Al, mb * 128, lda, k0, b + TILE_B);
        load_tile(Bh, nb * 128, ldb, k0, b + 2 * TILE_B);
        load_tile(Bl, nb * 128, ldb, k0, b + 3 * TILE_B);
        asm volatile("cp.async.commit_group;" ::: "memory");
    };
    auto compute = [&](int buf) {
        uint32_t b = sb + buf * BUF_B;
        #pragma unroll
        for (int s8 = 0; s8 < 4; s8++) {
            uint32_t ko = (uint32_t)(s8 * 32);
            uint32_t ah[4][4], al[4][4], bh[2][4], bl[2][4];
            #pragma unroll
            for (int i = 0; i < 4; i++) {
                ldsm4(ah[i], b + rowA[i] + ((ko + hA) ^ crA[i]));
                ldsm4(al[i], b + TILE_B + rowA[i] + ((ko + hA) ^ crA[i]));
            }
            #pragma unroll
            for (int jp = 0; jp < 2; jp++) {
                ldsm4(bh[jp], b + 2 * TILE_B + rowB[jp] + ((ko + hB) ^ crB[jp]));
                ldsm4(bl[jp], b + 3 * TILE_B + rowB[jp] + ((ko + hB) ^ crB[jp]));
            }
            #pragma unroll
            for (int i = 0; i < 4; i++)
                #pragma unroll
                for (int j = 0; j < 4; j++)
                    mma8(acc[i][j], ah[i], &bh[j >> 1][(j & 1) * 2]);
            #pragma unroll
            for (int i = 0; i < 4; i++)
                #pragma unroll
                for (int j = 0; j < 4; j++)
                    mma8(acc[i][j], al[i], &bh[j >> 1][(j & 1) * 2]);
            #pragma unroll
            for (int i = 0; i < 4; i++)
                #pragma unroll
                for (int j = 0; j < 4; j++)
                    mma8(acc[i][j], ah[i], &bl[j >> 1][(j & 1) * 2]);
        }
    };

    load_chunk(0, 0);
    load_chunk(1, 1);
    for (int ch = 0; ch < NCH; ch++) {
        int buf = ch & 1;
        if (ch == NCH - 1) asm volatile("cp.async.wait_group 0;" ::: "memory");
        else               asm volatile("cp.async.wait_group 1;" ::: "memory");
        __syncthreads();
        compute(buf);
        if (ch + 2 < NCH) {
            __syncthreads();
            load_chunk(ch + 2, buf);
        }
    }

    // epilogue: c0,c1 -> row gid cols 2*ctid..+1 ; c2,c3 -> row gid+8
    float* Cz = Cbase + (size_t)z * zstride;
    #pragma unroll
    for (int i = 0; i < 4; i++) {
        int row = mb * 128 + m0w + i * 16 + (lane >> 2);
        #pragma unroll
        for (int j = 0; j < 4; j++) {
            int col = nb * 128 + n0w + j * 8 + (lane & 3) * 2;
            float* p = Cz + (size_t)row * ldc + col;
            *(float2*)p              = make_float2(acc[i][j][0], acc[i][j][1]);
            *(float2*)(p + 8 * ldc)  = make_float2(acc[i][j][2], acc[i][j][3]);
        }
    }
}

// ---------------- weight transpose + tf32 split (once per launch) ----------------
__global__ void __launch_bounds__(256) prep_w1(const float* __restrict__ W1) {
    int o = blockIdx.x * 256 + threadIdx.x;       // out [n][k], in W1[k][n]
    int n = o >> 9, k = o & 511;
    tf32split(W1[(size_t)k * HID + n], g_W1Th[o], g_W1Tl[o]);
}
__global__ void __launch_bounds__(256) prep_w2(const float* __restrict__ W2) {
    int o = blockIdx.x * 256 + threadIdx.x;       // out [d][h], in W2[h][d]
    int d = o >> 11, h = o & 2047;
    tf32split(W2[(size_t)h * DIM + d], g_W2Th[o], g_W2Tl[o]);
}

// ---------------- A-prep for GEMM-G: split(Dy + c*kprev) ----------------
__global__ void __launch_bounds__(256) prep_ag(const float* __restrict__ kprev, int useprev,
                                               const float* __restrict__ ts, int interval, float cmul)
{
    int i = blockIdx.x * 256 + threadIdx.x;
    float x = g_Dy[i];
    if (useprev) {
        float c = cmul * (ts[interval+1] - ts[interval]) * (1.0f / SUBSTEPS);
        x += c * kprev[i];
    }
    tf32split(x, g_AhG[i], g_AlG[i]);
}

// ---------------- A-prep for GEMM-C: split(epi(G0+G1, a)) ----------------
__global__ void __launch_bounds__(256) prep_ac()
{
    int i = blockIdx.x * 256 + threadIdx.x;       // col = i & 2047
    float u = g_G[i] + g_G[(size_t)NBR * HID + i];
    float a = g_a[i & (HID - 1)];
    float s = 1.f - a * a;
    float v = s * u * (1.f - a * u);              // Jv + 0.5*Hvv epilogue
    tf32split(v, g_AhC[i], g_AlC[i]);
}

// ---------------- a = tanh((y + c*kprev) @ W1 + b1) ----------------
__global__ void __launch_bounds__(256) hcalc_kernel(
    const float* __restrict__ y, const float* __restrict__ kprev,
    const float* __restrict__ ts, int interval, float cmul,
    const float* __restrict__ W1, const float* __restrict__ b1,
    float* __restrict__ aout)
{
    __shared__ float ysh[DIM];
    __shared__ float red[256];
    int t = threadIdx.x;
    float dt = (ts[interval+1] - ts[interval]) * (1.0f / SUBSTEPS);
    float c = cmul * dt;
    ysh[t]       = y[t]       + c * kprev[t];
    ysh[t + 256] = y[t + 256] + c * kprev[t + 256];
    __syncthreads();
    int ds = t >> 6, jj = t & 63;
    int j = blockIdx.x * 64 + jj;
    const float* w = W1 + (size_t)(ds * 128) * HID + j;
    float h = 0.f;
    #pragma unroll 8
    for (int d = 0; d < 128; d++) h += ysh[ds*128 + d] * w[(size_t)d * HID];
    red[t] = h;
    __syncthreads();
    if (t < 64) {
        float hh = red[t] + red[t+64] + red[t+128] + red[t+192] + b1[j];
        aout[j] = tanhf(hh);
    }
}

// ---------------- dy = a @ W2 + b2 ----------------
__global__ void __launch_bounds__(256) dycalc_kernel(
    const float* __restrict__ avec, const float* __restrict__ W2,
    const float* __restrict__ b2, float* __restrict__ dyout)
{
    __shared__ float red[256];
    int t = threadIdx.x;
    int hs = t >> 5, dd = t & 31;
    int d = blockIdx.x * 32 + dd;
    const float* w  = W2 + (size_t)(hs * 256) * DIM + d;
    const float* av = avec + hs * 256;
    float acc = 0.f;
    #pragma unroll 8
    for (int h = 0; h < 256; h++) acc += av[h] * w[(size_t)h * DIM];
    red[t] = acc;
    __syncthreads();
    if (t < 32) {
        float s = 0.f;
        #pragma unroll
        for (int i = 0; i < 8; i++) s += red[dd + i*32];
        dyout[d] = s + b2[d];
    }
}

// ---------------- reduce the 8 GEMM-C split-K partials -> kDy[stage] ----------------
__global__ void __launch_bounds__(256) reduce_kernel(float* __restrict__ dst)
{
    int i = blockIdx.x * 256 + threadIdx.x;
    float s = 0.f;
    #pragma unroll
    for (int zz = 0; zz < 8; zz++) s += g_kDyP[(size_t)zz * ND + i];
    dst[i] = s;
}

// ---------------- RK4 combine ----------------
__global__ void __launch_bounds__(256) combine_kernel(const float* __restrict__ ts, int interval)
{
    int i = blockIdx.x * 256 + threadIdx.x;
    float dt = (ts[interval+1] - ts[interval]) * (1.0f / SUBSTEPS);
    float w = dt * (1.0f / 6.0f);
    if (i < ND) {
        float s = (g_kDy[i] + g_kDy[3*(size_t)ND + i])
                + 2.f * (g_kDy[(size_t)ND + i] + g_kDy[2*(size_t)ND + i]);
        g_Dy[i] += w * s;
    } else if (i < ND + DIM) {
        int d = i - ND;
        g_y[d] += w * (g_kdy[d] + 2.f*g_kdy[DIM + d] + 2.f*g_kdy[2*DIM + d] + g_kdy[3*DIM + d]);
    }
}

// ---------------- driver ----------------
extern "C" void kernel_launch(void* const* d_in, const int* in_sizes, int n_in,
                              void* d_out, int out_size)
{
    (void)in_sizes; (void)n_in; (void)out_size;
    const float* ts  = (const float*)d_in[0];
    const float* y0  = (const float*)d_in[1];
    const float* Dy0 = (const float*)d_in[2];
    const float* W1  = (const float*)d_in[3];
    const float* b1  = (const float*)d_in[4];
    const float* W2  = (const float*)d_in[5];
    const float* b2  = (const float*)d_in[6];
    float* out = (float*)d_out;

    float *y, *Dy, *a, *kdy, *kDy, *kDyP, *G;
    float *AhG, *AlG, *AhC, *AlC, *W1Th, *W1Tl, *W2Th, *W2Tl;
    cudaGetSymbolAddress((void**)&y,    g_y);
    cudaGetSymbolAddress((void**)&Dy,   g_Dy);
    cudaGetSymbolAddress((void**)&a,    g_a);
    cudaGetSymbolAddress((void**)&kdy,  g_kdy);
    cudaGetSymbolAddress((void**)&kDy,  g_kDy);
    cudaGetSymbolAddress((void**)&kDyP, g_kDyP);
    cudaGetSymbolAddress((void**)&G,    g_G);
    cudaGetSymbolAddress((void**)&AhG,  g_AhG);
    cudaGetSymbolAddress((void**)&AlG,  g_AlG);
    cudaGetSymbolAddress((void**)&AhC,  g_AhC);
    cudaGetSymbolAddress((void**)&AlC,  g_AlC);
    cudaGetSymbolAddress((void**)&W1Th, g_W1Th);
    cudaGetSymbolAddress((void**)&W1Tl, g_W1Tl);
    cudaGetSymbolAddress((void**)&W2Th, g_W2Th);
    cudaGetSymbolAddress((void**)&W2Tl, g_W2Tl);

    cudaFuncSetAttribute(gemm_mma, cudaFuncAttributeMaxDynamicSharedMemorySize, GEMM_SMEM);

    // init state + t=0 output slice
    cudaMemcpyAsync(y,  y0,  DIM*sizeof(float), cudaMemcpyDeviceToDevice, 0);
    cudaMemcpyAsync(Dy, Dy0, (size_t)ND*sizeof(float), cudaMemcpyDeviceToDevice, 0);
    cudaMemcpyAsync(out, y0, DIM*sizeof(float), cudaMemcpyDeviceToDevice, 0);
    cudaMemcpyAsync(out + DIM, Dy0, (size_t)ND*sizeof(float), cudaMemcpyDeviceToDevice, 0);

    // one-time weight transpose + tf32 split
    prep_w1<<<(HID*DIM)/256, 256>>>(W1);
    prep_w2<<<(DIM*HID)/256, 256>>>(W2);

    const float CM[4] = {0.f, 0.5f, 0.5f, 1.f};
    for (int interval = 0; interval < NSTEPS; interval++) {
        for (int sub = 0; sub < SUBSTEPS; sub++) {
            for (int s = 0; s < 4; s++) {
                const float* kprev = s ? (kdy + (size_t)(s-1)*DIM) : y;
                hcalc_kernel<<<32, 256>>>(y, kprev, ts, interval, CM[s], W1, b1, a);
                dycalc_kernel<<<16, 256>>>(a, W2, b2, kdy + (size_t)s*DIM);

                // A_G = Dy (+ c*kDy[s-1]), tf32-split
                prep_ag<<<ND/256, 256>>>(s ? (kDy + (size_t)(s-1)*ND) : nullptr, s ? 1 : 0,
                                         ts, interval, CM[s]);
                // G[z] = A_G @ W1 : M=512, N=2048, K=512 (z=2 x KSUB=256)
                gemm_mma<<<dim3(16,4,2), 256, GEMM_SMEM>>>(
                    AhG, AlG, DIM, W1Th, W1Tl, DIM, G, HID, (size_t)NBR*HID);
                // A_C = epi(G0+G1, a), tf32-split
                prep_ac<<<(NBR*HID)/256, 256>>>();
                // kDyP[z] = A_C @ W2 : M=512, N=512, K=2048 (z=8 x KSUB=256)
                gemm_mma<<<dim3(4,4,8), 256, GEMM_SMEM>>>(
                    AhC, AlC, HID, W2Th, W2Tl, HID, kDyP, DIM, (size_t)ND);
                reduce_kernel<<<ND/256, 256>>>(kDy + (size_t)s*ND);
            }
            combine_kernel<<<(ND + DIM + 255)/256, 256>>>(ts, interval);
        }
        float* dst = out + (size_t)(interval+1) * (1 + NBR) * DIM;
        cudaMemcpyAsync(dst, y, DIM*sizeof(float), cudaMemcpyDeviceToDevice, 0);
        cudaMemcpyAsync(dst + DIM, Dy, (size_t)ND*sizeof(float), cudaMemcpyDeviceToDevice, 0);
    }
}

// round 7
// speedup vs baseline: 3.0206x; 1.1645x over previous
#include <cuda_runtime.h>
#include <cstddef>
#include <cstdint>

#define DIM 512
#define HID 2048
#define NBR 512
#define ND (NBR*DIM)
#define NSTEPS 8
#define SUBSTEPS 2

// ---------------- device scratch (static allocation, allowed) ----------------
__device__ float g_y[DIM];
__device__ float g_Dy[ND];
__device__ float g_a[HID];
__device__ float g_kdy[4*DIM];
__device__ float g_kDy[4*ND];                 // reduced kDy per stage
__device__ float g_kDyP[8*ND];                // GEMM-C split-K partials (z=8)
__device__ float g_G[2*(size_t)NBR*HID];      // GEMM-G split-K partials (z=2), raw
__device__ float g_AhG[ND],       g_AlG[ND];        // tf32-split A for GEMM-G
__device__ float g_AhC[NBR*HID],  g_AlC[NBR*HID];   // tf32-split A for GEMM-C
__device__ float g_W1Th[(size_t)HID*DIM], g_W1Tl[(size_t)HID*DIM];  // W1^T split [2048x512]
__device__ float g_W2Th[(size_t)DIM*HID], g_W2Tl[(size_t)DIM*HID];  // W2^T split [512x2048]
__device__ float g_W1T[(size_t)HID*DIM];      // W1^T full fp32 (for matvec)
__device__ float g_W2T[(size_t)DIM*HID];      // W2^T full fp32 (for matvec)

// ---------------- PTX helpers (all sm_80 family-common; NO tcgen05) ----------------
static __device__ __forceinline__ uint32_t s2u(const void* p) {
    uint32_t a;
    asm("{ .reg .u64 t; cvta.to.shared.u64 t, %1; cvt.u32.u64 %0, t; }" : "=r"(a) : "l"(p));
    return a;
}
static __device__ __forceinline__ void cp16(uint32_t s, const void* g) {
    asm volatile("cp.async.cg.shared.global [%0], [%1], 16;" :: "r"(s), "l"(g));
}
static __device__ __forceinline__ uint32_t swz(uint32_t o) { return o ^ ((o >> 3) & 0x70); }

static __device__ __forceinline__ void ldsm4(uint32_t* r, uint32_t addr) {
    asm volatile("ldmatrix.sync.aligned.m8n8.x4.shared.b16 {%0,%1,%2,%3}, [%4];"
                 : "=r"(r[0]), "=r"(r[1]), "=r"(r[2]), "=r"(r[3]) : "r"(addr));
}
static __device__ __forceinline__ void mma8(float* c, const uint32_t* a, const uint32_t* b) {
    asm volatile("mma.sync.aligned.m16n8k8.row.col.f32.tf32.tf32.f32 "
                 "{%0,%1,%2,%3}, {%4,%5,%6,%7}, {%8,%9}, {%0,%1,%2,%3};"
                 : "+f"(c[0]), "+f"(c[1]), "+f"(c[2]), "+f"(c[3])
                 : "r"(a[0]), "r"(a[1]), "r"(a[2]), "r"(a[3]), "r"(b[0]), "r"(b[1]));
}

// tf32 hi/lo split: x ≈ h + l, both tf32-representable; product error ~2^-21
static __device__ __forceinline__ void tf32split(float x, float& h, float& l) {
    uint32_t hb; asm("cvt.rna.tf32.f32 %0, %1;" : "=r"(hb) : "f"(x));
    float hf = __uint_as_float(hb);
    float r = x - hf;
    uint32_t lb; asm("cvt.rna.tf32.f32 %0, %1;" : "=r"(lb) : "f"(r));
    h = hf; l = __uint_as_float(lb);
}

// ---------------- mma.sync tf32 GEMM, 3-pass split: AhBh + AlBh + AhBl ----------------
#define KCH 32
#define NCH 8
#define KSUB 256
#define TILE_B (128*KCH*4)
#define BUF_B (4*TILE_B)
#define GEMM_SMEM (2*BUF_B)

__global__ void __launch_bounds__(256, 1)
gemm_mma(const float* __restrict__ Ah, const float* __restrict__ Al, int lda,
         const float* __restrict__ Bh, const float* __restrict__ Bl, int ldb,
         float* __restrict__ Cbase, int ldc, size_t zstride)
{
    extern __shared__ __align__(1024) char smem[];
    const uint32_t sb = s2u(smem);
    const int t = threadIdx.x, lane = t & 31, wid = t >> 5;
    const int nb = blockIdx.x, mb = blockIdx.y, z = blockIdx.z;
    const int kbase = z * KSUB;
    const int m0w = (wid & 1) * 64, n0w = (wid >> 1) * 32;

    const int rAl = (lane & 7) + ((lane >> 3) & 1) * 8;
    const int hA  = (lane >> 4) * 16;
    const int rBl = (lane & 7) + ((lane >> 4) & 1) * 8;
    const int hB  = ((lane >> 3) & 1) * 16;
    uint32_t rowA[4], crA[4], rowB[2], crB[2];
    #pragma unroll
    for (int i = 0; i < 4; i++) {
        int row = m0w + i * 16 + rAl;
        rowA[i] = (uint32_t)row * 128u; crA[i] = (uint32_t)(row & 7) * 16u;
    }
    #pragma unroll
    for (int jp = 0; jp < 2; jp++) {
        int row = n0w + jp * 16 + rBl;
        rowB[jp] = (uint32_t)row * 128u; crB[jp] = (uint32_t)(row & 7) * 16u;
    }

    float acc[4][4][4];
    #pragma unroll
    for (int i = 0; i < 4; i++)
        #pragma unroll
        for (int j = 0; j < 4; j++)
            #pragma unroll
            for (int q = 0; q < 4; q++) acc[i][j][q] = 0.f;

    auto load_tile = [&](const float* src, int rowbase, int ld, int k0, uint32_t sdst) {
        #pragma unroll
        for (int i = 0; i < 4; i++) {
            int id = i * 256 + t;
            int r = id >> 3, c = id & 7;
            cp16(sdst + swz((uint32_t)(r * 128 + c * 16)),
                 src + (size_t)(rowbase + r) * ld + k0 + c * 4);
        }
    };
    auto load_chunk = [&](int ch, int buf) {
        int k0 = kbase + ch * KCH;
        uint32_t b = sb + buf * BUF_B;
        load_tile(Ah, mb * 128, lda, k0, b);
        load_tile(Al, mb * 128, lda, k0, b + TILE_B);
        load_tile(Bh, nb * 128, ldb, k0, b + 2 * TILE_B);
        load_tile(Bl, nb * 128, ldb, k0, b + 3 * TILE_B);
        asm volatile("cp.async.commit_group;" ::: "memory");
    };
    auto compute = [&](int buf) {
        uint32_t b = sb + buf * BUF_B;
        #pragma unroll
        for (int s8 = 0; s8 < 4; s8++) {
            uint32_t ko = (uint32_t)(s8 * 32);
            uint32_t ah[4][4], al[4][4], bh[2][4], bl[2][4];
            #pragma unroll
            for (int i = 0; i < 4; i++) {
                ldsm4(ah[i], b + rowA[i] + ((ko + hA) ^ crA[i]));
                ldsm4(al[i], b + TILE_B + rowA[i] + ((ko + hA) ^ crA[i]));
            }
            #pragma unroll
            for (int jp = 0; jp < 2; jp++) {
                ldsm4(bh[jp], b + 2 * TILE_B + rowB[jp] + ((ko + hB) ^ crB[jp]));
                ldsm4(bl[jp], b + 3 * TILE_B + rowB[jp] + ((ko + hB) ^ crB[jp]));
            }
            #pragma unroll
            for (int i = 0; i < 4; i++)
                #pragma unroll
                for (int j = 0; j < 4; j++)
                    mma8(acc[i][j], ah[i], &bh[j >> 1][(j & 1) * 2]);
            #pragma unroll
            for (int i = 0; i < 4; i++)
                #pragma unroll
                for (int j = 0; j < 4; j++)
                    mma8(acc[i][j], al[i], &bh[j >> 1][(j & 1) * 2]);
            #pragma unroll
            for (int i = 0; i < 4; i++)
                #pragma unroll
                for (int j = 0; j < 4; j++)
                    mma8(acc[i][j], ah[i], &bl[j >> 1][(j & 1) * 2]);
        }
    };

    load_chunk(0, 0);
    load_chunk(1, 1);
    for (int ch = 0; ch < NCH; ch++) {
        int buf = ch & 1;
        if (ch == NCH - 1) asm volatile("cp.async.wait_group 0;" ::: "memory");
        else               asm volatile("cp.async.wait_group 1;" ::: "memory");
        __syncthreads();
        compute(buf);
        if (ch + 2 < NCH) {
            __syncthreads();
            load_chunk(ch + 2, buf);
        }
    }

    float* Cz = Cbase + (size_t)z * zstride;
    #pragma unroll
    for (int i = 0; i < 4; i++) {
        int row = mb * 128 + m0w + i * 16 + (lane >> 2);
        #pragma unroll
        for (int j = 0; j < 4; j++) {
            int col = nb * 128 + n0w + j * 8 + (lane & 3) * 2;
            float* p = Cz + (size_t)row * ldc + col;
            *(float2*)p              = make_float2(acc[i][j][0], acc[i][j][1]);
            *(float2*)(p + 8 * ldc)  = make_float2(acc[i][j][2], acc[i][j][3]);
        }
    }
}

// ---------------- weight transpose + tf32 split (+ full fp32 transpose) ----------------
__global__ void __launch_bounds__(256) prep_w1(const float* __restrict__ W1) {
    int o = blockIdx.x * 256 + threadIdx.x;       // out [n][k], in W1[k][n]
    int n = o >> 9, k = o & 511;
    float v = W1[(size_t)k * HID + n];
    g_W1T[o] = v;
    tf32split(v, g_W1Th[o], g_W1Tl[o]);
}
__global__ void __launch_bounds__(256) prep_w2(const float* __restrict__ W2) {
    int o = blockIdx.x * 256 + threadIdx.x;       // out [d][h], in W2[h][d]
    int d = o >> 11, h = o & 2047;
    float v = W2[(size_t)h * DIM + d];
    g_W2T[o] = v;
    tf32split(v, g_W2Th[o], g_W2Tl[o]);
}

// ---------------- A-prep for GEMM-G: split(Dy + c*kprev) ----------------
__global__ void __launch_bounds__(256) prep_ag(const float* __restrict__ kprev, int useprev,
                                               const float* __restrict__ ts, int interval, float cmul)
{
    int i = blockIdx.x * 256 + threadIdx.x;
    float x = g_Dy[i];
    if (useprev) {
        float c = cmul * (ts[interval+1] - ts[interval]) * (1.0f / SUBSTEPS);
        x += c * kprev[i];
    }
    tf32split(x, g_AhG[i], g_AlG[i]);
}

// ---------------- A-prep for GEMM-C: split(epi(G0+G1, a)) ----------------
__global__ void __launch_bounds__(256) prep_ac()
{
    int i = blockIdx.x * 256 + threadIdx.x;       // col = i & 2047
    float u = g_G[i] + g_G[(size_t)NBR * HID + i];
    float a = g_a[i & (HID - 1)];
    float s = 1.f - a * a;
    float v = s * u * (1.f - a * u);              // Jv + 0.5*Hvv epilogue
    tf32split(v, g_AhC[i], g_AlC[i]);
}

// ---------------- a = tanh((y + c*kprev) @ W1 + b1), warp-per-output ----------------
// grid 256 x 256thr: 8 warps/block, each warp one j (2048 total); W1T rows contiguous.
__global__ void __launch_bounds__(256) hcalc2_kernel(
    const float* __restrict__ y, const float* __restrict__ kprev,
    const float* __restrict__ ts, int interval, float cmul,
    const float* __restrict__ b1, float* __restrict__ aout)
{
    __shared__ float ysh[DIM];
    int t = threadIdx.x, lane = t & 31, wid = t >> 5;
    float dt = (ts[interval+1] - ts[interval]) * (1.0f / SUBSTEPS);
    float c = cmul * dt;
    ysh[t]       = y[t]       + c * kprev[t];
    ysh[t + 256] = y[t + 256] + c * kprev[t + 256];
    __syncthreads();
    int j = blockIdx.x * 8 + wid;
    const float4* w4 = (const float4*)(g_W1T + (size_t)j * DIM);
    const float4* y4 = (const float4*)ysh;
    float acc = 0.f;
    #pragma unroll
    for (int i = 0; i < 4; i++) {              // 512 floats = 4 x 32 lanes x float4
        float4 wv = w4[lane + i * 32];
        float4 yv = y4[lane + i * 32];
        acc += wv.x*yv.x + wv.y*yv.y + wv.z*yv.z + wv.w*yv.w;
    }
    #pragma unroll
    for (int o = 16; o > 0; o >>= 1) acc += __shfl_xor_sync(0xffffffffu, acc, o);
    if (lane == 0) aout[j] = tanhf(acc + b1[j]);
}

// ---------------- dy = a @ W2 + b2, warp-per-output ----------------
// grid 64 x 256thr: 8 warps/block, each warp one d (512 total); W2T rows contiguous.
__global__ void __launch_bounds__(256) dycalc2_kernel(
    const float* __restrict__ avec, const float* __restrict__ b2,
    float* __restrict__ dyout)
{
    __shared__ float ash[HID];
    int t = threadIdx.x, lane = t & 31, wid = t >> 5;
    #pragma unroll
    for (int i = 0; i < 2; i++)
        *(float4*)&ash[(t + i * 256) * 4] = *(const float4*)&avec[(t + i * 256) * 4];
    __syncthreads();
    int d = blockIdx.x * 8 + wid;
    const float4* w4 = (const float4*)(g_W2T + (size_t)d * HID);
    const float4* a4 = (const float4*)ash;
    float acc = 0.f;
    #pragma unroll
    for (int i = 0; i < 16; i++) {             // 2048 floats = 16 x 32 lanes x float4
        float4 wv = w4[lane + i * 32];
        float4 av = a4[lane + i * 32];
        acc += wv.x*av.x + wv.y*av.y + wv.z*av.z + wv.w*av.w;
    }
    #pragma unroll
    for (int o = 16; o > 0; o >>= 1) acc += __shfl_xor_sync(0xffffffffu, acc, o);
    if (lane == 0) dyout[d] = acc + b2[d];
}

// ---------------- reduce the 8 GEMM-C split-K partials -> kDy[stage] ----------------
__global__ void __launch_bounds__(256) reduce_kernel(float* __restrict__ dst)
{
    int i = blockIdx.x * 256 + threadIdx.x;
    float s = 0.f;
    #pragma unroll
    for (int zz = 0; zz < 8; zz++) s += g_kDyP[(size_t)zz * ND + i];
    dst[i] = s;
}

// ---------------- RK4 combine ----------------
__global__ void __launch_bounds__(256) combine_kernel(const float* __restrict__ ts, int interval)
{
    int i = blockIdx.x * 256 + threadIdx.x;
    float dt = (ts[interval+1] - ts[interval]) * (1.0f / SUBSTEPS);
    float w = dt * (1.0f / 6.0f);
    if (i < ND) {
        float s = (g_kDy[i] + g_kDy[3*(size_t)ND + i])
                + 2.f * (g_kDy[(size_t)ND + i] + g_kDy[2*(size_t)ND + i]);
        g_Dy[i] += w * s;
    } else if (i < ND + DIM) {
        int d = i - ND;
        g_y[d] += w * (g_kdy[d] + 2.f*g_kdy[DIM + d] + 2.f*g_kdy[2*DIM + d] + g_kdy[3*DIM + d]);
    }
}

// ---------------- driver ----------------
extern "C" void kernel_launch(void* const* d_in, const int* in_sizes, int n_in,
                              void* d_out, int out_size)
{
    (void)in_sizes; (void)n_in; (void)out_size;
    const float* ts  = (const float*)d_in[0];
    const float* y0  = (const float*)d_in[1];
    const float* Dy0 = (const float*)d_in[2];
    const float* W1  = (const float*)d_in[3];
    const float* b1  = (const float*)d_in[4];
    const float* W2  = (const float*)d_in[5];
    const float* b2  = (const float*)d_in[6];
    float* out = (float*)d_out;

    float *y, *Dy, *a, *kdy, *kDy, *kDyP, *G;
    float *AhG, *AlG, *AhC, *AlC, *W1Th, *W1Tl, *W2Th, *W2Tl;
    cudaGetSymbolAddress((void**)&y,    g_y);
    cudaGetSymbolAddress((void**)&Dy,   g_Dy);
    cudaGetSymbolAddress((void**)&a,    g_a);
    cudaGetSymbolAddress((void**)&kdy,  g_kdy);
    cudaGetSymbolAddress((void**)&kDy,  g_kDy);
    cudaGetSymbolAddress((void**)&kDyP, g_kDyP);
    cudaGetSymbolAddress((void**)&G,    g_G);
    cudaGetSymbolAddress((void**)&AhG,  g_AhG);
    cudaGetSymbolAddress((void**)&AlG,  g_AlG);
    cudaGetSymbolAddress((void**)&AhC,  g_AhC);
    cudaGetSymbolAddress((void**)&AlC,  g_AlC);
    cudaGetSymbolAddress((void**)&W1Th, g_W1Th);
    cudaGetSymbolAddress((void**)&W1Tl, g_W1Tl);
    cudaGetSymbolAddress((void**)&W2Th, g_W2Th);
    cudaGetSymbolAddress((void**)&W2Tl, g_W2Tl);

    cudaFuncSetAttribute(gemm_mma, cudaFuncAttributeMaxDynamicSharedMemorySize, GEMM_SMEM);

    // init state + t=0 output slice
    cudaMemcpyAsync(y,  y0,  DIM*sizeof(float), cudaMemcpyDeviceToDevice, 0);
    cudaMemcpyAsync(Dy, Dy0, (size_t)ND*sizeof(float), cudaMemcpyDeviceToDevice, 0);
    cudaMemcpyAsync(out, y0, DIM*sizeof(float), cudaMemcpyDeviceToDevice, 0);
    cudaMemcpyAsync(out + DIM, Dy0, (size_t)ND*sizeof(float), cudaMemcpyDeviceToDevice, 0);

    // one-time weight transpose + tf32 split + full transpose
    prep_w1<<<(HID*DIM)/256, 256>>>(W1);
    prep_w2<<<(DIM*HID)/256, 256>>>(W2);

    const float CM[4] = {0.f, 0.5f, 0.5f, 1.f};
    for (int interval = 0; interval < NSTEPS; interval++) {
        for (int sub = 0; sub < SUBSTEPS; sub++) {
            for (int s = 0; s < 4; s++) {
                const float* kprev = s ? (kdy + (size_t)(s-1)*DIM) : y;
                hcalc2_kernel<<<256, 256>>>(y, kprev, ts, interval, CM[s], b1, a);
                dycalc2_kernel<<<64, 256>>>(a, b2, kdy + (size_t)s*DIM);

                // A_G = Dy (+ c*kDy[s-1]), tf32-split
                prep_ag<<<ND/256, 256>>>(s ? (kDy + (size_t)(s-1)*ND) : nullptr, s ? 1 : 0,
                                         ts, interval, CM[s]);
                // G[z] = A_G @ W1 : M=512, N=2048, K=512 (z=2 x KSUB=256)
                gemm_mma<<<dim3(16,4,2), 256, GEMM_SMEM>>>(
                    AhG, AlG, DIM, W1Th, W1Tl, DIM, G, HID, (size_t)NBR*HID);
                // A_C = epi(G0+G1, a), tf32-split
                prep_ac<<<(NBR*HID)/256, 256>>>();
                // kDyP[z] = A_C @ W2 : M=512, N=512, K=2048 (z=8 x KSUB=256)
                gemm_mma<<<dim3(4,4,8), 256, GEMM_SMEM>>>(
                    AhC, AlC, HID, W2Th, W2Tl, HID, kDyP, DIM, (size_t)ND);
                reduce_kernel<<<ND/256, 256>>>(kDy + (size_t)s*ND);
            }
            combine_kernel<<<(ND + DIM + 255)/256, 256>>>(ts, interval);
        }
        float* dst = out + (size_t)(interval+1) * (1 + NBR) * DIM;
        cudaMemcpyAsync(dst, y, DIM*sizeof(float), cudaMemcpyDeviceToDevice, 0);
        cudaMemcpyAsync(dst + DIM, Dy, (size_t)ND*sizeof(float), cudaMemcpyDeviceToDevice, 0);
    }
}